// round 7
// baseline (speedup 1.0000x reference)
#include <cuda_runtime.h>

#define Wn 262144
#define Ln 32
#define Nn (Ln * Wn)
#define CAP 2048   // queue capacity; expected total tree ~63 entries

// Linear DAG cone evaluation, single warp, two dependency hops per iteration.
// root = sum over path-tree leaves of (prod path weights) * values[leaf] * w_term.
__global__ void __launch_bounds__(32) cone_kernel(
    const float* __restrict__ values,
    const int2*  __restrict__ idx2,     // child_idx as [L-1,W] int2
    const int*   __restrict__ types,    // node_types [L-1,W]
    const float* __restrict__ w_term,
    const float* __restrict__ w_plus,
    const float* __restrict__ w_minus,
    const float* __restrict__ w_final,
    const float* __restrict__ b_final,
    float* __restrict__ out)
{
    __shared__ int2 s_q[CAP];           // (node id, coef bits)

    const int lane = threadIdx.x;
    const unsigned below = (1u << lane) - 1u;
    const float2 P = *(const float2*)w_plus;
    const float2 M = *(const float2*)w_minus;

    float acc = 0.0f;
    int head = 0, tail = 1;             // warp-uniform cursors (no atomics)
    if (lane == 0) s_q[0] = make_int2(Nn - 1, __float_as_int(1.0f));
    __syncwarp();

    int cnt = 1;
    for (int iter = 0; iter < 64 && cnt > 0; iter++) {
        int   n = 0;                    // nonterminal grandchildren produced by this lane
        int   qv[4];
        float qc[4];

        if (lane < cnt) {
            int2 e = s_q[head + lane];  // claimed entry: guaranteed nonterminal
            int   v = e.x;
            float c = __int_as_float(e.y);

            // hop 1: this node's children
            int base = v - Wn;
            int2 ch = __ldg(&idx2[base]);
            int  t  = __ldg(&types[base]);
            float c0 = c * ((t == 1) ? P.x : M.x);
            float c1 = c * ((t == 1) ? P.y : M.y);

            // hop 2: expand each child in the same iteration (independent loads)
            if (ch.x < Wn) {
                acc += c0 * __ldg(&values[ch.x]);            // terminal, overlapped
            } else {
                int b2 = ch.x - Wn;
                int2 g  = __ldg(&idx2[b2]);
                int  t2 = __ldg(&types[b2]);
                float d0 = c0 * ((t2 == 1) ? P.x : M.x);
                float d1 = c0 * ((t2 == 1) ? P.y : M.y);
                if (g.x < Wn) acc += d0 * __ldg(&values[g.x]);
                else { qv[n] = g.x; qc[n] = d0; n++; }
                if (g.y < Wn) acc += d1 * __ldg(&values[g.y]);
                else { qv[n] = g.y; qc[n] = d1; n++; }
            }
            if (ch.y < Wn) {
                acc += c1 * __ldg(&values[ch.y]);
            } else {
                int b3 = ch.y - Wn;
                int2 g  = __ldg(&idx2[b3]);
                int  t3 = __ldg(&types[b3]);
                float d0 = c1 * ((t3 == 1) ? P.x : M.x);
                float d1 = c1 * ((t3 == 1) ? P.y : M.y);
                if (g.x < Wn) acc += d0 * __ldg(&values[g.x]);
                else { qv[n] = g.x; qc[n] = d0; n++; }
                if (g.y < Wn) acc += d1 * __ldg(&values[g.y]);
                else { qv[n] = g.y; qc[n] = d1; n++; }
            }
        }
        head += cnt;

        // Ballot prefix-sum of per-lane counts (n in 0..4) -> write positions
        unsigned B0 = __ballot_sync(0xFFFFFFFFu, n & 1);
        unsigned B1 = __ballot_sync(0xFFFFFFFFu, n & 2);
        unsigned B2 = __ballot_sync(0xFFFFFFFFu, n & 4);
        int off = __popc(B0 & below) + 2 * __popc(B1 & below) + 4 * __popc(B2 & below);
        int T   = __popc(B0) + 2 * __popc(B1) + 4 * __popc(B2);

        int p = tail + off;
        #pragma unroll
        for (int i = 0; i < 4; i++)
            if (i < n && p + i < CAP)
                s_q[p + i] = make_int2(qv[i], __float_as_int(qc[i]));
        tail = min(tail + T, CAP);      // overflow drops (never expected; verify catches)

        __syncwarp();                    // queue writes visible for next claims
        cnt = min(32, tail - head);
    }

    // Warp reduction of partial sums
    #pragma unroll
    for (int s = 16; s > 0; s >>= 1)
        acc += __shfl_xor_sync(0xFFFFFFFFu, acc, s);

    if (lane == 0) {
        float root = acc * __ldg(w_term);
        out[0] = fmaf(root, __ldg(w_final), __ldg(b_final));
    }
}

extern "C" void kernel_launch(void* const* d_in, const int* in_sizes, int n_in,
                              void* d_out, int out_size) {
    const float* values     = (const float*)d_in[0];
    const int*   child_idx  = (const int*)d_in[1];   // [L-1, W, 2]
    const int*   node_types = (const int*)d_in[2];   // [L-1, W]
    const float* w_term     = (const float*)d_in[3];
    const float* w_plus     = (const float*)d_in[4];
    const float* w_minus    = (const float*)d_in[5];
    const float* w_final    = (const float*)d_in[6];
    const float* b_final    = (const float*)d_in[7];
    float* out = (float*)d_out;

    cone_kernel<<<1, 32>>>(values,
                           (const int2*)child_idx,
                           node_types,
                           w_term, w_plus, w_minus, w_final, b_final,
                           out);
}

// round 8
// speedup vs baseline: 1.0332x; 1.0332x over previous
#include <cuda_runtime.h>

#define Wn 262144
#define Ln 32
#define Nn (Ln * Wn)
#define CAP 2048   // queue holds nonterminals only; expected ~32 total

// Linear DAG cone evaluation, single warp, one dependency hop per iteration.
// root = sum over path-tree leaves of (prod path weights) * values[leaf] * w_term.
// Terminals are folded in at fork time; only nonterminals are queued.
__global__ void __launch_bounds__(32) cone_kernel(
    const float* __restrict__ values,
    const int2*  __restrict__ idx2,     // child_idx as [L-1,W] int2
    const int*   __restrict__ types,    // node_types [L-1,W]
    const float* __restrict__ w_term,
    const float* __restrict__ w_plus,
    const float* __restrict__ w_minus,
    const float* __restrict__ w_final,
    const float* __restrict__ b_final,
    float* __restrict__ out)
{
    __shared__ int2 s_q[CAP];           // (node id, coef bits), nonterminals only

    const int lane = threadIdx.x;
    const unsigned below = (1u << lane) - 1u;
    const float2 P = *(const float2*)w_plus;
    const float2 M = *(const float2*)w_minus;

    float acc = 0.0f;
    int head = 0, tail = 1;             // warp-uniform cursors, no atomics
    if (lane == 0) s_q[0] = make_int2(Nn - 1, __float_as_int(1.0f));
    __syncwarp();

    int cnt = 1;
    for (int iter = 0; iter < 64 && cnt > 0; iter++) {
        int   n = 0;                    // nonterminal children produced (0..2)
        int   qv0 = 0, qv1 = 0;
        float qc0 = 0.f, qc1 = 0.f;

        if (lane < cnt) {
            int2 e = s_q[head + lane];  // entry is guaranteed nonterminal
            int base = e.x - Wn;        // (l-1)*W + off
            float c = __int_as_float(e.y);

            int2 ch = __ldg(&idx2[base]);   // the dependent gather
            int  t  = __ldg(&types[base]);  // independent, overlapped
            float c0 = c * ((t == 1) ? P.x : M.x);
            float c1 = c * ((t == 1) ? P.y : M.y);

            if (ch.x < Wn) acc += c0 * __ldg(&values[ch.x]);   // terminal inline
            else { qv0 = ch.x; qc0 = c0; n = 1; }
            if (ch.y < Wn) acc += c1 * __ldg(&values[ch.y]);
            else { if (n) { qv1 = ch.y; qc1 = c1; } else { qv0 = ch.y; qc0 = c1; } n++; }
        }
        head += cnt;

        // Ballot prefix-sum over n in {0,1,2}
        unsigned B0 = __ballot_sync(0xFFFFFFFFu, n & 1);
        unsigned B1 = __ballot_sync(0xFFFFFFFFu, n & 2);
        int off = __popc(B0 & below) + 2 * __popc(B1 & below);
        int T   = __popc(B0) + 2 * __popc(B1);

        int p = tail + off;
        if (n >= 1 && p < CAP)     s_q[p]     = make_int2(qv0, __float_as_int(qc0));
        if (n == 2 && p + 1 < CAP) s_q[p + 1] = make_int2(qv1, __float_as_int(qc1));
        tail = min(tail + T, CAP);  // overflow never expected; verify would catch

        __syncwarp();               // queue writes visible before next claims
        cnt = min(32, tail - head);
    }

    // Warp reduction
    #pragma unroll
    for (int s = 16; s > 0; s >>= 1)
        acc += __shfl_xor_sync(0xFFFFFFFFu, acc, s);

    if (lane == 0) {
        float root = acc * __ldg(w_term);
        out[0] = fmaf(root, __ldg(w_final), __ldg(b_final));
    }
}

extern "C" void kernel_launch(void* const* d_in, const int* in_sizes, int n_in,
                              void* d_out, int out_size) {
    const float* values     = (const float*)d_in[0];
    const int*   child_idx  = (const int*)d_in[1];   // [L-1, W, 2]
    const int*   node_types = (const int*)d_in[2];   // [L-1, W]
    const float* w_term     = (const float*)d_in[3];
    const float* w_plus     = (const float*)d_in[4];
    const float* w_minus    = (const float*)d_in[5];
    const float* w_final    = (const float*)d_in[6];
    const float* b_final    = (const float*)d_in[7];
    float* out = (float*)d_out;

    cone_kernel<<<1, 32>>>(values,
                           (const int2*)child_idx,
                           node_types,
                           w_term, w_plus, w_minus, w_final, b_final,
                           out);
}